// round 10
// baseline (speedup 1.0000x reference)
#include <cuda_runtime.h>
#include <math_constants.h>

// Problem constants (KnnEdges: B=4, M=8192, D=2, k=16)
#define B_   4
#define M_   8192
#define N_   (B_ * M_)          // 32768
#define K_   16
#define NE_  (N_ * K_)          // 524288

// Spatial grid: cell = 16.0 (power of two -> exact binning/bounds), 63x63 cells
#define G_    63
#define GG_   (G_ * G_)         // 3969
#define INVH_ 0.0625f

// Output layout (float32 concat of reference tuple)
#define OFF_X     0
#define OFF_POSP  2097152
#define OFF_EIDX  2162688
#define OFF_EW    3211264
#define OFF_BATCH 3735552
#define OFF_PERM  3768320
#define OFF_SCORE 3801088

typedef unsigned long long u64;

__device__ int      g_cnt[B_][GG_ + 1];  // counts -> starts; zeroed by norm (prev call) / static init
__device__ int      g_rank[N_];          // per-point rank within its cell
__device__ float4   g_pts[N_];           // grid-sorted (x, y, idx_bits, 0)
__device__ unsigned g_maxbits;           // zeroed by scan (before knn)

__device__ __forceinline__ int cell_of(float v) {
    int c = (int)(v * INVH_);
    return c > G_ - 1 ? G_ - 1 : (c < 0 ? 0 : c);
}

// ---------------------------------------------------------------------------
// K1: copies/casts + pos gather + cell counting (rank saved for atomic-free
// scatter). Requires g_cnt == 0 on entry (norm of previous call / static).
// batch/perm are int32 on device (JAX x64 disabled).
// ---------------------------------------------------------------------------
__global__ void prep_kernel(const float* __restrict__ x,
                            const float* __restrict__ pos,
                            const int* __restrict__ perm,
                            const float* __restrict__ score,
                            float* __restrict__ out) {
    int t = blockIdx.x * blockDim.x + threadIdx.x;

    const int C0 = (N_ * 64) / 16;         // 131072: x copy, 4 float4 each (ILP)
    if (t < C0) {
        const float4* xs = (const float4*)x;
        float4* xd = (float4*)(out + OFF_X);
        float4 a = xs[t], b = xs[t + C0], c = xs[t + 2 * C0], d = xs[t + 3 * C0];
        xd[t] = a; xd[t + C0] = b; xd[t + 2 * C0] = c; xd[t + 3 * C0] = d;
        return;
    }
    t -= C0;
    if (t < N_) {                          // pos gather + cell count
        int p = perm[t];
        float2 v = ((const float2*)pos)[p];
        ((float2*)(out + OFF_POSP))[t] = v;
        int b = t >> 13;
        int c = cell_of(v.y) * G_ + cell_of(v.x);
        g_rank[t] = atomicAdd(&g_cnt[b][c], 1);
        return;
    }
    t -= N_;
    if (t < NE_ / 4) {                     // tgt row of edge_index, float4
        int base = 4 * t;
        ((float4*)(out + OFF_EIDX + NE_))[t] =
            make_float4((float)(base >> 4), (float)((base + 1) >> 4),
                        (float)((base + 2) >> 4), (float)((base + 3) >> 4));
        return;
    }
    t -= NE_ / 4;
    if (t < N_ / 4) {                      // batch cast, float4
        int base = 4 * t;
        ((float4*)(out + OFF_BATCH))[t] =
            make_float4((float)(base >> 13), (float)((base + 1) >> 13),
                        (float)((base + 2) >> 13), (float)((base + 3) >> 13));
        return;
    }
    t -= N_ / 4;
    if (t < N_ / 4) {                      // perm cast, float4
        int4 p = ((const int4*)perm)[t];
        ((float4*)(out + OFF_PERM))[t] =
            make_float4((float)p.x, (float)p.y, (float)p.z, (float)p.w);
        return;
    }
    t -= N_ / 4;
    if (t < N_ / 4) {                      // score copy, float4
        ((float4*)(out + OFF_SCORE))[t] = ((const float4*)score)[t];
        return;
    }
}

// ---------------------------------------------------------------------------
// K2: per-batch exclusive prefix sum over cell counts (one CTA per batch).
// Also zeroes g_maxbits for this call's knn.
// ---------------------------------------------------------------------------
__global__ void __launch_bounds__(1024) scan_kernel() {
    __shared__ int sh[1024];
    const int b = blockIdx.x;
    const int t = threadIdx.x;
    const int base = t * 4;

    if (b == 0 && t == 0) g_maxbits = 0u;

    int v[4], tot = 0;
#pragma unroll
    for (int i = 0; i < 4; i++) {
        v[i] = (base + i < GG_) ? g_cnt[b][base + i] : 0;
        tot += v[i];
    }
    sh[t] = tot;
    __syncthreads();
    for (int off = 1; off < 1024; off <<= 1) {
        int u = (t >= off) ? sh[t - off] : 0;
        __syncthreads();
        sh[t] += u;
        __syncthreads();
    }
    int run = sh[t] - tot;   // exclusive
#pragma unroll
    for (int i = 0; i < 4; i++) {
        if (base + i < GG_) g_cnt[b][base + i] = run;
        run += v[i];
    }
    if (t == 1023) g_cnt[b][GG_] = run;   // = M_
}

// ---------------------------------------------------------------------------
// K3: scatter points into grid-sorted order using saved ranks (no atomics).
// ---------------------------------------------------------------------------
__global__ void __launch_bounds__(256) scatter_kernel(const float* __restrict__ out) {
    int t = blockIdx.x * blockDim.x + threadIdx.x;
    if (t >= N_) return;
    int b = t >> 13, i = t & (M_ - 1);
    float2 v = ((const float2*)(out + OFF_POSP))[t];
    int c = cell_of(v.y) * G_ + cell_of(v.x);
    int dst = g_cnt[b][c] + g_rank[t];
    g_pts[b * M_ + dst] = make_float4(v.x, v.y, __int_as_float(i), 0.0f);
}

// ---------------------------------------------------------------------------
// K4: exact KNN, 8 cooperative lanes per query (262144 threads).
// - Lanes split candidates WITHIN each cell (j = js+lane, step 8): all lanes
//   walk identical cells -> convergent control flow; per-lane serial
//   inner-loop work is 1/8 of the candidate count.
// - Each lane keeps a sorted top-16 of packed u64 keys (d2_bits<<32 | idx)
//   in registers; predicated full bubble on insert (NO data-dependent break).
//   Integer key order == lexicographic (d2 asc, idx asc) == top_k(-d2) order.
// - Ring break: sum over 8 lanes of #(d2 strictly < ((r-1)*16)^2) >= 16 is
//   exactly equivalent to "true 16th-best < bound^2" (lanes hold disjoint
//   candidates; a lane that dropped any candidate < B2 holds 16 keys < B2).
// - Merge (exact, in-place, 2 temps; proven R8/R9): three rounds (XOR 1,2,4).
//   Per round, for i<8 read partner's ORIGINAL key[15-i], key[i] (each index
//   written exactly once at its own iteration; lockstep shuffles precede
//   writes):
//     key[i]    = min(A[i],    B[15-i]);  key[15-i] = min(A[15-i], B[i])
//   => key[j] = min(A[j], B[15-j]) for all j: the 16 smallest of the union in
//   bitonic order; 4-stage bitonic network re-sorts. After the 3 rounds all
//   8 lanes hold the identical sorted global top-16.
// - d2 uses explicit rn ops (no FMA) to bit-match XLA's sub/mul/mul/add.
// ---------------------------------------------------------------------------
__global__ void __launch_bounds__(256) knn_kernel(float* __restrict__ out) {
    const int t     = blockIdx.x * 256 + threadIdx.x;
    const int group = t >> 3;          // query id
    const int lane  = t & 7;
    const int b     = group >> 13;
    const int s     = group & (M_ - 1);

    const float4* __restrict__ pts = g_pts + b * M_;
    const int*    __restrict__ cs  = g_cnt[b];

    float4 q = pts[s];
    const int qi = __float_as_int(q.z);
    const int cx = cell_of(q.x), cy = cell_of(q.y);

    u64 key[K_];
#pragma unroll
    for (int u = 0; u < K_; u++) key[u] = 0xFFFFFFFFFFFFFFFFull;

    bool done = false;

#define VISIT(XX, YY)                                                          \
    {                                                                          \
        int c_ = (YY) * G_ + (XX);                                             \
        int js_ = cs[c_], je_ = cs[c_ + 1];                                    \
        for (int j_ = js_ + lane; j_ < je_; j_ += 8) {                         \
            float4 v_ = pts[j_];                                               \
            float dx_ = __fsub_rn(q.x, v_.x);                                  \
            float dy_ = __fsub_rn(q.y, v_.y);                                  \
            float d2_ = __fadd_rn(__fmul_rn(dx_, dx_), __fmul_rn(dy_, dy_));   \
            u64 nk_ = ((u64)__float_as_uint(d2_) << 32) |                      \
                      (unsigned)__float_as_int(v_.z);                          \
            if (nk_ < key[K_ - 1]) {                                           \
                key[K_ - 1] = nk_;                                             \
                _Pragma("unroll")                                              \
                for (int u_ = K_ - 1; u_ > 0; u_--) {                          \
                    if (key[u_] < key[u_ - 1]) {                               \
                        u64 tm_ = key[u_]; key[u_] = key[u_ - 1];              \
                        key[u_ - 1] = tm_;                                     \
                    }                                                          \
                }                                                              \
            }                                                                  \
        }                                                                      \
    }

    for (int r = 0; r < G_; r++) {
        if (r >= 2) {
            float bnd = (float)(r - 1) * 16.0f;     // exact in fp
            float B2 = bnd * bnd;
            int cnt = 0;
#pragma unroll
            for (int u = 0; u < K_; u++)
                cnt += (__uint_as_float((unsigned)(key[u] >> 32)) < B2) ? 1 : 0;
            cnt += __shfl_xor_sync(0xffffffffu, cnt, 1);
            cnt += __shfl_xor_sync(0xffffffffu, cnt, 2);
            cnt += __shfl_xor_sync(0xffffffffu, cnt, 4);
            if (cnt >= K_) done = true;
        }
        if (__all_sync(0xffffffffu, done)) break;
        if (!done) {
            int x0 = cx - r, x1 = cx + r, y0 = cy - r, y1 = cy + r;
            int xa = x0 < 0 ? 0 : x0, xb = x1 > G_ - 1 ? G_ - 1 : x1;
            if (r == 0) {
                VISIT(cx, cy);
            } else {
                if (y0 >= 0)
                    for (int xx = xa; xx <= xb; xx++) VISIT(xx, y0);
                if (y1 <= G_ - 1)
                    for (int xx = xa; xx <= xb; xx++) VISIT(xx, y1);
                int ya = (y0 + 1) < 0 ? 0 : (y0 + 1);
                int yb = (y1 - 1) > G_ - 1 ? G_ - 1 : (y1 - 1);
                for (int yy = ya; yy <= yb; yy++) {
                    if (x0 >= 0)      VISIT(x0, yy);
                    if (x1 <= G_ - 1) VISIT(x1, yy);
                }
            }
        }
    }
#undef VISIT

    // Three rounds of exact in-place cross-lane merge + bitonic re-sort.
#pragma unroll
    for (int mask = 1; mask <= 4; mask <<= 1) {
#pragma unroll
        for (int i = 0; i < K_ / 2; i++) {
            u64 oa = __shfl_xor_sync(0xffffffffu, key[K_ - 1 - i], mask); // B[15-i]
            u64 ob = __shfl_xor_sync(0xffffffffu, key[i], mask);          // B[i]
            u64 a_lo = key[i], a_hi = key[K_ - 1 - i];
            key[i]          = a_lo < oa ? a_lo : oa;   // min(A[i],    B[15-i])
            key[K_ - 1 - i] = a_hi < ob ? a_hi : ob;   // min(A[15-i], B[i])
        }
#pragma unroll
        for (int st = 8; st >= 1; st >>= 1) {
#pragma unroll
            for (int i = 0; i < K_; i++) {
                if ((i & st) == 0) {
                    u64 a = key[i], c = key[i + st];
                    key[i] = a < c ? a : c;
                    key[i + st] = a < c ? c : a;
                }
            }
        }
    }

    // Each lane writes its eighth (entries 2*lane, 2*lane+1), coalesced 8B.
    u64 e0, e1;
    switch (lane) {
        case 0: e0 = key[0];  e1 = key[1];  break;
        case 1: e0 = key[2];  e1 = key[3];  break;
        case 2: e0 = key[4];  e1 = key[5];  break;
        case 3: e0 = key[6];  e1 = key[7];  break;
        case 4: e0 = key[8];  e1 = key[9];  break;
        case 5: e0 = key[10]; e1 = key[11]; break;
        case 6: e0 = key[12]; e1 = key[13]; break;
        default: e0 = key[14]; e1 = key[15]; break;
    }

    const int tgt = b * M_ + qi;
    float f0 = __fsqrt_rn(__uint_as_float((unsigned)(e0 >> 32)));
    float f1 = __fsqrt_rn(__uint_as_float((unsigned)(e1 >> 32)));

    ((float2*)(out + OFF_EIDX))[tgt * 8 + lane] =
        make_float2((float)(b * M_ + (int)(e0 & 0xFFFFFFFFu)),
                    (float)(b * M_ + (int)(e1 & 0xFFFFFFFFu)));
    ((float2*)(out + OFF_EW))[tgt * 8 + lane] = make_float2(f0, f1);

    // Global max: key[15] is this query's largest kept distance (identical on
    // all 8 lanes post-merge). Warp-reduce then one atomic per warp.
    float lm = __fsqrt_rn(__uint_as_float((unsigned)(key[K_ - 1] >> 32)));
#pragma unroll
    for (int off = 16; off; off >>= 1)
        lm = fmaxf(lm, __shfl_xor_sync(0xffffffffu, lm, off));
    if ((threadIdx.x & 31) == 0)
        atomicMax(&g_maxbits, __float_as_uint(lm));
}

// ---------------------------------------------------------------------------
// K5: normalize edge weights; also zero g_cnt for the NEXT call
// (g_cnt is not read by this kernel -> no ordering hazard).
// ---------------------------------------------------------------------------
__global__ void norm_kernel(float* __restrict__ out) {
    int t = blockIdx.x * blockDim.x + threadIdx.x;
    if (t < B_ * (GG_ + 1)) ((int*)g_cnt)[t] = 0;
    if (t < NE_ / 4) {
        float m = __uint_as_float(g_maxbits);
        float4 v = ((const float4*)(out + OFF_EW))[t];
        ((float4*)(out + OFF_EW))[t] =
            make_float4(v.x / m, v.y / m, v.z / m, v.w / m);
    }
}

extern "C" void kernel_launch(void* const* d_in, const int* in_sizes, int n_in,
                              void* d_out, int out_size) {
    const float* x     = (const float*)d_in[0];
    const float* pos   = (const float*)d_in[1];
    const int*   perm  = (const int*)d_in[5];
    const float* score = (const float*)d_in[6];
    float* out = (float*)d_out;

    const int prep_threads = (N_ * 64) / 16 + N_ + NE_ / 4 + 3 * (N_ / 4);
    prep_kernel<<<prep_threads / 256, 256>>>(x, pos, perm, score, out);

    scan_kernel<<<B_, 1024>>>();
    scatter_kernel<<<N_ / 256, 256>>>(out);
    knn_kernel<<<(8 * N_) / 256, 256>>>(out);     // 8 lanes/query, within-cell split
    norm_kernel<<<(NE_ / 4) / 256, 256>>>(out);
}

// round 11
// speedup vs baseline: 1.3254x; 1.3254x over previous
#include <cuda_runtime.h>
#include <math_constants.h>

// Problem constants (KnnEdges: B=4, M=8192, D=2, k=16)
#define B_   4
#define M_   8192
#define N_   (B_ * M_)          // 32768
#define K_   16
#define NE_  (N_ * K_)          // 524288

// Spatial grid: cell = 16.0 (power of two -> exact binning/bounds), 63x63 cells
#define G_    63
#define GG_   (G_ * G_)         // 3969
#define INVH_ 0.0625f

// Output layout (float32 concat of reference tuple)
#define OFF_X     0
#define OFF_POSP  2097152
#define OFF_EIDX  2162688
#define OFF_EW    3211264
#define OFF_BATCH 3735552
#define OFF_PERM  3768320
#define OFF_SCORE 3801088

typedef unsigned long long u64;

__device__ int      g_cnt[B_][GG_ + 1];  // counts -> starts; zeroed by norm (prev call) / static init
__device__ int      g_rank[N_];          // per-point rank within its cell
__device__ float4   g_pts[N_];           // grid-sorted (x, y, idx_bits, 0)
__device__ unsigned g_maxbits;           // zeroed by scan (before knn)

__device__ __forceinline__ int cell_of(float v) {
    int c = (int)(v * INVH_);
    return c > G_ - 1 ? G_ - 1 : (c < 0 ? 0 : c);
}

// ---------------------------------------------------------------------------
// K1: copies/casts + pos gather + cell counting (rank saved for atomic-free
// scatter). Requires g_cnt == 0 on entry (norm of previous call / static).
// batch/perm are int32 on device (JAX x64 disabled).
// ---------------------------------------------------------------------------
__global__ void prep_kernel(const float* __restrict__ x,
                            const float* __restrict__ pos,
                            const int* __restrict__ perm,
                            const float* __restrict__ score,
                            float* __restrict__ out) {
    int t = blockIdx.x * blockDim.x + threadIdx.x;

    const int C0 = (N_ * 64) / 16;         // 131072: x copy, 4 float4 each (ILP)
    if (t < C0) {
        const float4* xs = (const float4*)x;
        float4* xd = (float4*)(out + OFF_X);
        float4 a = xs[t], b = xs[t + C0], c = xs[t + 2 * C0], d = xs[t + 3 * C0];
        xd[t] = a; xd[t + C0] = b; xd[t + 2 * C0] = c; xd[t + 3 * C0] = d;
        return;
    }
    t -= C0;
    if (t < N_) {                          // pos gather + cell count
        int p = perm[t];
        float2 v = ((const float2*)pos)[p];
        ((float2*)(out + OFF_POSP))[t] = v;
        int b = t >> 13;
        int c = cell_of(v.y) * G_ + cell_of(v.x);
        g_rank[t] = atomicAdd(&g_cnt[b][c], 1);
        return;
    }
    t -= N_;
    if (t < NE_ / 4) {                     // tgt row of edge_index, float4
        int base = 4 * t;
        ((float4*)(out + OFF_EIDX + NE_))[t] =
            make_float4((float)(base >> 4), (float)((base + 1) >> 4),
                        (float)((base + 2) >> 4), (float)((base + 3) >> 4));
        return;
    }
    t -= NE_ / 4;
    if (t < N_ / 4) {                      // batch cast, float4
        int base = 4 * t;
        ((float4*)(out + OFF_BATCH))[t] =
            make_float4((float)(base >> 13), (float)((base + 1) >> 13),
                        (float)((base + 2) >> 13), (float)((base + 3) >> 13));
        return;
    }
    t -= N_ / 4;
    if (t < N_ / 4) {                      // perm cast, float4
        int4 p = ((const int4*)perm)[t];
        ((float4*)(out + OFF_PERM))[t] =
            make_float4((float)p.x, (float)p.y, (float)p.z, (float)p.w);
        return;
    }
    t -= N_ / 4;
    if (t < N_ / 4) {                      // score copy, float4
        ((float4*)(out + OFF_SCORE))[t] = ((const float4*)score)[t];
        return;
    }
}

// ---------------------------------------------------------------------------
// K2: per-batch exclusive prefix sum over cell counts (one CTA per batch).
// Also zeroes g_maxbits for this call's knn.
// ---------------------------------------------------------------------------
__global__ void __launch_bounds__(1024) scan_kernel() {
    __shared__ int sh[1024];
    const int b = blockIdx.x;
    const int t = threadIdx.x;
    const int base = t * 4;

    if (b == 0 && t == 0) g_maxbits = 0u;

    int v[4], tot = 0;
#pragma unroll
    for (int i = 0; i < 4; i++) {
        v[i] = (base + i < GG_) ? g_cnt[b][base + i] : 0;
        tot += v[i];
    }
    sh[t] = tot;
    __syncthreads();
    for (int off = 1; off < 1024; off <<= 1) {
        int u = (t >= off) ? sh[t - off] : 0;
        __syncthreads();
        sh[t] += u;
        __syncthreads();
    }
    int run = sh[t] - tot;   // exclusive
#pragma unroll
    for (int i = 0; i < 4; i++) {
        if (base + i < GG_) g_cnt[b][base + i] = run;
        run += v[i];
    }
    if (t == 1023) g_cnt[b][GG_] = run;   // = M_
}

// ---------------------------------------------------------------------------
// K3: scatter points into grid-sorted order using saved ranks (no atomics).
// ---------------------------------------------------------------------------
__global__ void __launch_bounds__(256) scatter_kernel(const float* __restrict__ out) {
    int t = blockIdx.x * blockDim.x + threadIdx.x;
    if (t >= N_) return;
    int b = t >> 13, i = t & (M_ - 1);
    float2 v = ((const float2*)(out + OFF_POSP))[t];
    int c = cell_of(v.y) * G_ + cell_of(v.x);
    int dst = g_cnt[b][c] + g_rank[t];
    g_pts[b * M_ + dst] = make_float4(v.x, v.y, __int_as_float(i), 0.0f);
}

// ---------------------------------------------------------------------------
// K4: exact KNN, 4 cooperative lanes per query (131072 threads).
// - Lanes split candidates WITHIN each cell (j = js+lane, step 4): convergent
//   control flow; per-lane serial work = 1/4 of candidates.
// - Sorted per-lane top-16 of packed u64 keys (d2_bits<<32 | idx); predicated
//   full bubble on insert. Key order == (d2 asc, idx asc) == top_k(-d2).
// - EXACT early-reject gate (new): X = max over the 4 lanes of key[3]
//   (recomputed each ring, warp-uniform shuffles). The union of lanes' top-4s
//   is 16 real keys, so globalTop16thKey <= X at all times. Any final global
//   top-16 member m arriving at a lane satisfies:
//     (a) m < its lane's current key[15]  (else 16 lane keys < m => 16 global
//         keys < m => m not in global top-16), and
//     (b) m < X  (m <= g16 <= X; equality impossible: keys are distinct --
//         unique candidate idx -- and m is not yet stored anywhere).
//   Hence skipping candidates with d2_bits > hi32(min(key[15]@ring-start, X))
//   never drops a needed key (high-32 equality falls through to the exact
//   check). Insert condition itself (nk < key[15]) is unchanged.
// - Ring break: sum over lanes of #(kept keys < ((r-1)*16)^2) >= 16. Kept
//   lists always contain the global top-16 (shown above), so this certifies
//   and triggers at the same ring as the unpruned version. Exact.
// - Merge (exact, in-place, 2 temps; proven R8/R9): two rounds (XOR 1, 2).
// - d2 uses explicit rn ops (no FMA) to bit-match XLA's sub/mul/mul/add.
// ---------------------------------------------------------------------------
__global__ void __launch_bounds__(128) knn_kernel(float* __restrict__ out) {
    const int t     = blockIdx.x * 128 + threadIdx.x;
    const int group = t >> 2;          // query id
    const int lane  = t & 3;
    const int b     = group >> 13;
    const int s     = group & (M_ - 1);

    const float4* __restrict__ pts = g_pts + b * M_;
    const int*    __restrict__ cs  = g_cnt[b];

    float4 q = pts[s];
    const int qi = __float_as_int(q.z);
    const int cx = cell_of(q.x), cy = cell_of(q.y);

    u64 key[K_];
#pragma unroll
    for (int u = 0; u < K_; u++) key[u] = 0xFFFFFFFFFFFFFFFFull;

    unsigned gate_hi = 0xFFFFFFFFu;    // hi32 of min(key[15]@ring-start, X)
    bool done = false;

#define VISIT(XX, YY)                                                          \
    {                                                                          \
        int c_ = (YY) * G_ + (XX);                                             \
        int js_ = cs[c_], je_ = cs[c_ + 1];                                    \
        for (int j_ = js_ + lane; j_ < je_; j_ += 4) {                         \
            float4 v_ = pts[j_];                                               \
            float dx_ = __fsub_rn(q.x, v_.x);                                  \
            float dy_ = __fsub_rn(q.y, v_.y);                                  \
            float d2_ = __fadd_rn(__fmul_rn(dx_, dx_), __fmul_rn(dy_, dy_));   \
            unsigned d2u_ = __float_as_uint(d2_);                              \
            if (d2u_ <= gate_hi) {                                             \
                u64 nk_ = ((u64)d2u_ << 32) |                                  \
                          (unsigned)__float_as_int(v_.z);                      \
                if (nk_ < key[K_ - 1]) {                                       \
                    key[K_ - 1] = nk_;                                         \
                    _Pragma("unroll")                                          \
                    for (int u_ = K_ - 1; u_ > 0; u_--) {                      \
                        if (key[u_] < key[u_ - 1]) {                           \
                            u64 tm_ = key[u_]; key[u_] = key[u_ - 1];          \
                            key[u_ - 1] = tm_;                                 \
                        }                                                      \
                    }                                                          \
                }                                                              \
            }                                                                  \
        }                                                                      \
    }

    for (int r = 0; r < G_; r++) {
        // Warp-uniform section: termination + gate update (shuffles live here).
        if (r >= 2) {
            float bnd = (float)(r - 1) * 16.0f;     // exact in fp
            float B2 = bnd * bnd;
            int cnt = 0;
#pragma unroll
            for (int u = 0; u < K_; u++)
                cnt += (__uint_as_float((unsigned)(key[u] >> 32)) < B2) ? 1 : 0;
            cnt += __shfl_xor_sync(0xffffffffu, cnt, 1);
            cnt += __shfl_xor_sync(0xffffffffu, cnt, 2);
            if (cnt >= K_) done = true;
        }
        if (__all_sync(0xffffffffu, done)) break;

        // X = max over 4 lanes of key[3]; gate = min(key[15], X) (hi 32 bits).
        {
            u64 x3 = key[3];
            u64 o = __shfl_xor_sync(0xffffffffu, x3, 1);
            if (o > x3) x3 = o;
            o = __shfl_xor_sync(0xffffffffu, x3, 2);
            if (o > x3) x3 = o;
            u64 g = key[K_ - 1] < x3 ? key[K_ - 1] : x3;
            gate_hi = (unsigned)(g >> 32);
        }

        if (!done) {
            int x0 = cx - r, x1 = cx + r, y0 = cy - r, y1 = cy + r;
            int xa = x0 < 0 ? 0 : x0, xb = x1 > G_ - 1 ? G_ - 1 : x1;
            if (r == 0) {
                VISIT(cx, cy);
            } else {
                if (y0 >= 0)
                    for (int xx = xa; xx <= xb; xx++) VISIT(xx, y0);
                if (y1 <= G_ - 1)
                    for (int xx = xa; xx <= xb; xx++) VISIT(xx, y1);
                int ya = (y0 + 1) < 0 ? 0 : (y0 + 1);
                int yb = (y1 - 1) > G_ - 1 ? G_ - 1 : (y1 - 1);
                for (int yy = ya; yy <= yb; yy++) {
                    if (x0 >= 0)      VISIT(x0, yy);
                    if (x1 <= G_ - 1) VISIT(x1, yy);
                }
            }
        }
    }
#undef VISIT

    // Two rounds of exact in-place cross-lane merge + bitonic re-sort.
#pragma unroll
    for (int mask = 1; mask <= 2; mask <<= 1) {
#pragma unroll
        for (int i = 0; i < K_ / 2; i++) {
            u64 oa = __shfl_xor_sync(0xffffffffu, key[K_ - 1 - i], mask); // B[15-i]
            u64 ob = __shfl_xor_sync(0xffffffffu, key[i], mask);          // B[i]
            u64 a_lo = key[i], a_hi = key[K_ - 1 - i];
            key[i]          = a_lo < oa ? a_lo : oa;   // min(A[i],    B[15-i])
            key[K_ - 1 - i] = a_hi < ob ? a_hi : ob;   // min(A[15-i], B[i])
        }
#pragma unroll
        for (int st = 8; st >= 1; st >>= 1) {
#pragma unroll
            for (int i = 0; i < K_; i++) {
                if ((i & st) == 0) {
                    u64 a = key[i], c = key[i + st];
                    key[i] = a < c ? a : c;
                    key[i + st] = a < c ? c : a;
                }
            }
        }
    }

    // Each lane writes its quarter (entries 4*lane .. 4*lane+3), coalesced 16B.
    u64 e0, e1, e2, e3;
    if (lane == 0)      { e0 = key[0];  e1 = key[1];  e2 = key[2];  e3 = key[3];  }
    else if (lane == 1) { e0 = key[4];  e1 = key[5];  e2 = key[6];  e3 = key[7];  }
    else if (lane == 2) { e0 = key[8];  e1 = key[9];  e2 = key[10]; e3 = key[11]; }
    else                { e0 = key[12]; e1 = key[13]; e2 = key[14]; e3 = key[15]; }

    const int tgt = b * M_ + qi;
    float f0 = __fsqrt_rn(__uint_as_float((unsigned)(e0 >> 32)));
    float f1 = __fsqrt_rn(__uint_as_float((unsigned)(e1 >> 32)));
    float f2 = __fsqrt_rn(__uint_as_float((unsigned)(e2 >> 32)));
    float f3 = __fsqrt_rn(__uint_as_float((unsigned)(e3 >> 32)));

    ((float4*)(out + OFF_EIDX))[tgt * 4 + lane] =
        make_float4((float)(b * M_ + (int)(e0 & 0xFFFFFFFFu)),
                    (float)(b * M_ + (int)(e1 & 0xFFFFFFFFu)),
                    (float)(b * M_ + (int)(e2 & 0xFFFFFFFFu)),
                    (float)(b * M_ + (int)(e3 & 0xFFFFFFFFu)));
    ((float4*)(out + OFF_EW))[tgt * 4 + lane] = make_float4(f0, f1, f2, f3);

    // Global max: key[15] is this query's largest kept distance (identical on
    // all 4 lanes post-merge). Warp-reduce then one atomic per warp.
    float lm = __fsqrt_rn(__uint_as_float((unsigned)(key[K_ - 1] >> 32)));
#pragma unroll
    for (int off = 16; off; off >>= 1)
        lm = fmaxf(lm, __shfl_xor_sync(0xffffffffu, lm, off));
    if ((threadIdx.x & 31) == 0)
        atomicMax(&g_maxbits, __float_as_uint(lm));
}

// ---------------------------------------------------------------------------
// K5: normalize edge weights; also zero g_cnt for the NEXT call
// (g_cnt is not read by this kernel -> no ordering hazard).
// ---------------------------------------------------------------------------
__global__ void norm_kernel(float* __restrict__ out) {
    int t = blockIdx.x * blockDim.x + threadIdx.x;
    if (t < B_ * (GG_ + 1)) ((int*)g_cnt)[t] = 0;
    if (t < NE_ / 4) {
        float m = __uint_as_float(g_maxbits);
        float4 v = ((const float4*)(out + OFF_EW))[t];
        ((float4*)(out + OFF_EW))[t] =
            make_float4(v.x / m, v.y / m, v.z / m, v.w / m);
    }
}

extern "C" void kernel_launch(void* const* d_in, const int* in_sizes, int n_in,
                              void* d_out, int out_size) {
    const float* x     = (const float*)d_in[0];
    const float* pos   = (const float*)d_in[1];
    const int*   perm  = (const int*)d_in[5];
    const float* score = (const float*)d_in[6];
    float* out = (float*)d_out;

    const int prep_threads = (N_ * 64) / 16 + N_ + NE_ / 4 + 3 * (N_ / 4);
    prep_kernel<<<prep_threads / 256, 256>>>(x, pos, perm, score, out);

    scan_kernel<<<B_, 1024>>>();
    scatter_kernel<<<N_ / 256, 256>>>(out);
    knn_kernel<<<(4 * N_) / 128, 128>>>(out);     // 4 lanes/query, gated inserts
    norm_kernel<<<(NE_ / 4) / 256, 256>>>(out);
}

// round 12
// speedup vs baseline: 1.6781x; 1.2662x over previous
#include <cuda_runtime.h>
#include <math_constants.h>

// Problem constants (KnnEdges: B=4, M=8192, D=2, k=16)
#define B_   4
#define M_   8192
#define N_   (B_ * M_)          // 32768
#define K_   16
#define NE_  (N_ * K_)          // 524288

// Spatial grid: cell = 16.0 (power of two -> exact binning/bounds), 63x63 cells
#define G_    63
#define GG_   (G_ * G_)         // 3969
#define INVH_ 0.0625f

// Output layout (float32 concat of reference tuple)
#define OFF_X     0
#define OFF_POSP  2097152
#define OFF_EIDX  2162688
#define OFF_EW    3211264
#define OFF_BATCH 3735552
#define OFF_PERM  3768320
#define OFF_SCORE 3801088

typedef unsigned long long u64;

__device__ int      g_cnt[B_][GG_ + 1];  // counts -> starts; zeroed by norm (prev call) / static init
__device__ int      g_rank[N_];          // per-point rank within its cell
__device__ float4   g_pts[N_];           // grid-sorted (x, y, idx_bits, 0)
__device__ unsigned g_maxbits;           // zeroed by scan (before knn)

__device__ __forceinline__ int cell_of(float v) {
    int c = (int)(v * INVH_);
    return c > G_ - 1 ? G_ - 1 : (c < 0 ? 0 : c);
}

// ---------------------------------------------------------------------------
// K1: copies/casts + pos gather + cell counting (rank saved for atomic-free
// scatter). Requires g_cnt == 0 on entry (norm of previous call / static).
// batch/perm are int32 on device (JAX x64 disabled).
// ---------------------------------------------------------------------------
__global__ void prep_kernel(const float* __restrict__ x,
                            const float* __restrict__ pos,
                            const int* __restrict__ perm,
                            const float* __restrict__ score,
                            float* __restrict__ out) {
    int t = blockIdx.x * blockDim.x + threadIdx.x;

    const int C0 = (N_ * 64) / 16;         // 131072: x copy, 4 float4 each (ILP)
    if (t < C0) {
        const float4* xs = (const float4*)x;
        float4* xd = (float4*)(out + OFF_X);
        float4 a = xs[t], b = xs[t + C0], c = xs[t + 2 * C0], d = xs[t + 3 * C0];
        xd[t] = a; xd[t + C0] = b; xd[t + 2 * C0] = c; xd[t + 3 * C0] = d;
        return;
    }
    t -= C0;
    if (t < N_) {                          // pos gather + cell count
        int p = perm[t];
        float2 v = ((const float2*)pos)[p];
        ((float2*)(out + OFF_POSP))[t] = v;
        int b = t >> 13;
        int c = cell_of(v.y) * G_ + cell_of(v.x);
        g_rank[t] = atomicAdd(&g_cnt[b][c], 1);
        return;
    }
    t -= N_;
    if (t < NE_ / 4) {                     // tgt row of edge_index, float4
        int base = 4 * t;
        ((float4*)(out + OFF_EIDX + NE_))[t] =
            make_float4((float)(base >> 4), (float)((base + 1) >> 4),
                        (float)((base + 2) >> 4), (float)((base + 3) >> 4));
        return;
    }
    t -= NE_ / 4;
    if (t < N_ / 4) {                      // batch cast, float4
        int base = 4 * t;
        ((float4*)(out + OFF_BATCH))[t] =
            make_float4((float)(base >> 13), (float)((base + 1) >> 13),
                        (float)((base + 2) >> 13), (float)((base + 3) >> 13));
        return;
    }
    t -= N_ / 4;
    if (t < N_ / 4) {                      // perm cast, float4
        int4 p = ((const int4*)perm)[t];
        ((float4*)(out + OFF_PERM))[t] =
            make_float4((float)p.x, (float)p.y, (float)p.z, (float)p.w);
        return;
    }
    t -= N_ / 4;
    if (t < N_ / 4) {                      // score copy, float4
        ((float4*)(out + OFF_SCORE))[t] = ((const float4*)score)[t];
        return;
    }
}

// ---------------------------------------------------------------------------
// K2: per-batch exclusive prefix sum over cell counts (one CTA per batch).
// Also zeroes g_maxbits for this call's knn.
// ---------------------------------------------------------------------------
__global__ void __launch_bounds__(1024) scan_kernel() {
    __shared__ int sh[1024];
    const int b = blockIdx.x;
    const int t = threadIdx.x;
    const int base = t * 4;

    if (b == 0 && t == 0) g_maxbits = 0u;

    int v[4], tot = 0;
#pragma unroll
    for (int i = 0; i < 4; i++) {
        v[i] = (base + i < GG_) ? g_cnt[b][base + i] : 0;
        tot += v[i];
    }
    sh[t] = tot;
    __syncthreads();
    for (int off = 1; off < 1024; off <<= 1) {
        int u = (t >= off) ? sh[t - off] : 0;
        __syncthreads();
        sh[t] += u;
        __syncthreads();
    }
    int run = sh[t] - tot;   // exclusive
#pragma unroll
    for (int i = 0; i < 4; i++) {
        if (base + i < GG_) g_cnt[b][base + i] = run;
        run += v[i];
    }
    if (t == 1023) g_cnt[b][GG_] = run;   // = M_
}

// ---------------------------------------------------------------------------
// K3: scatter points into grid-sorted order using saved ranks (no atomics).
// ---------------------------------------------------------------------------
__global__ void __launch_bounds__(256) scatter_kernel(const float* __restrict__ out) {
    int t = blockIdx.x * blockDim.x + threadIdx.x;
    if (t >= N_) return;
    int b = t >> 13, i = t & (M_ - 1);
    float2 v = ((const float2*)(out + OFF_POSP))[t];
    int c = cell_of(v.y) * G_ + cell_of(v.x);
    int dst = g_cnt[b][c] + g_rank[t];
    g_pts[b * M_ + dst] = make_float4(v.x, v.y, __int_as_float(i), 0.0f);
}

// ---------------------------------------------------------------------------
// K4: exact KNN, 4 cooperative lanes per query, ROW-SEGMENT scanning.
// - A ring row of W consecutive cells is ONE contiguous range
//   [cs[c0], cs[c0+W]) in the grid-sorted array -> one bookkeeping step per
//   row (vs per cell), and lanes split candidates within the SEGMENT
//   (j = js+lane, step 4) so all 4 lanes stay busy even though cells hold
//   only ~2 points each. Convergent control flow (lanes differ only in j).
// - Sorted per-lane top-16 of packed u64 keys (d2_bits<<32 | idx); predicated
//   full bubble on insert. Key order == (d2 asc, idx asc) == top_k(-d2).
// - EXACT early-reject gate (proven R11): X = max over the 4 lanes of key[3]
//   (per-ring, warp-uniform). Union of lanes' top-4s = 16 real keys =>
//   globalTop16thKey <= X. Any final global top-16 member m arriving at a
//   lane satisfies m < its lane's key[15] (else 16 global keys < m) and
//   m < X. Hence skipping candidates with d2_bits > hi32(min(key[15], X))
//   never drops a needed key (hi-32 equality falls through to exact check).
// - Ring break: sum over lanes of #(kept keys < ((r-1)*16)^2) >= 16; kept
//   lists always contain the global top-16, so exact.
// - Merge (exact, in-place, 2 temps; proven R8/R9): two rounds (XOR 1, 2).
// - d2 uses explicit rn ops (no FMA) to bit-match XLA's sub/mul/mul/add.
// ---------------------------------------------------------------------------
__global__ void __launch_bounds__(128) knn_kernel(float* __restrict__ out) {
    const int t     = blockIdx.x * 128 + threadIdx.x;
    const int group = t >> 2;          // query id
    const int lane  = t & 3;
    const int b     = group >> 13;
    const int s     = group & (M_ - 1);

    const float4* __restrict__ pts = g_pts + b * M_;
    const int*    __restrict__ cs  = g_cnt[b];

    float4 q = pts[s];
    const int qi = __float_as_int(q.z);
    const int cx = cell_of(q.x), cy = cell_of(q.y);

    u64 key[K_];
#pragma unroll
    for (int u = 0; u < K_; u++) key[u] = 0xFFFFFFFFFFFFFFFFull;

    unsigned gate_hi = 0xFFFFFFFFu;    // hi32 of min(key[15]@ring-start, X)
    bool done = false;

// One contiguous row segment of cells [XA..XB] in row YY.
#define VISIT_SEG(XA, XB, YY)                                                  \
    {                                                                          \
        int c0_ = (YY) * G_ + (XA);                                            \
        int js_ = cs[c0_], je_ = cs[c0_ + ((XB) - (XA)) + 1];                  \
        for (int j_ = js_ + lane; j_ < je_; j_ += 4) {                         \
            float4 v_ = pts[j_];                                               \
            float dx_ = __fsub_rn(q.x, v_.x);                                  \
            float dy_ = __fsub_rn(q.y, v_.y);                                  \
            float d2_ = __fadd_rn(__fmul_rn(dx_, dx_), __fmul_rn(dy_, dy_));   \
            unsigned d2u_ = __float_as_uint(d2_);                              \
            if (d2u_ <= gate_hi) {                                             \
                u64 nk_ = ((u64)d2u_ << 32) |                                  \
                          (unsigned)__float_as_int(v_.z);                      \
                if (nk_ < key[K_ - 1]) {                                       \
                    key[K_ - 1] = nk_;                                         \
                    _Pragma("unroll")                                          \
                    for (int u_ = K_ - 1; u_ > 0; u_--) {                      \
                        if (key[u_] < key[u_ - 1]) {                           \
                            u64 tm_ = key[u_]; key[u_] = key[u_ - 1];          \
                            key[u_ - 1] = tm_;                                 \
                        }                                                      \
                    }                                                          \
                }                                                              \
            }                                                                  \
        }                                                                      \
    }

    for (int r = 0; r < G_; r++) {
        // Warp-uniform section: termination + gate update (shuffles live here).
        if (r >= 2) {
            float bnd = (float)(r - 1) * 16.0f;     // exact in fp
            float B2 = bnd * bnd;
            int cnt = 0;
#pragma unroll
            for (int u = 0; u < K_; u++)
                cnt += (__uint_as_float((unsigned)(key[u] >> 32)) < B2) ? 1 : 0;
            cnt += __shfl_xor_sync(0xffffffffu, cnt, 1);
            cnt += __shfl_xor_sync(0xffffffffu, cnt, 2);
            if (cnt >= K_) done = true;
        }
        if (__all_sync(0xffffffffu, done)) break;

        // X = max over 4 lanes of key[3]; gate = min(key[15], X) (hi 32 bits).
        {
            u64 x3 = key[3];
            u64 o = __shfl_xor_sync(0xffffffffu, x3, 1);
            if (o > x3) x3 = o;
            o = __shfl_xor_sync(0xffffffffu, x3, 2);
            if (o > x3) x3 = o;
            u64 g = key[K_ - 1] < x3 ? key[K_ - 1] : x3;
            gate_hi = (unsigned)(g >> 32);
        }

        if (!done) {
            int x0 = cx - r, x1 = cx + r, y0 = cy - r, y1 = cy + r;
            int xa = x0 < 0 ? 0 : x0, xb = x1 > G_ - 1 ? G_ - 1 : x1;
            if (r == 0) {
                VISIT_SEG(cx, cx, cy);
            } else {
                if (y0 >= 0)      VISIT_SEG(xa, xb, y0);   // top row
                if (y1 <= G_ - 1) VISIT_SEG(xa, xb, y1);   // bottom row
                int ya = (y0 + 1) < 0 ? 0 : (y0 + 1);
                int yb = (y1 - 1) > G_ - 1 ? G_ - 1 : (y1 - 1);
                for (int yy = ya; yy <= yb; yy++) {        // side columns
                    if (x0 >= 0)      VISIT_SEG(x0, x0, yy);
                    if (x1 <= G_ - 1) VISIT_SEG(x1, x1, yy);
                }
            }
        }
    }
#undef VISIT_SEG

    // Two rounds of exact in-place cross-lane merge + bitonic re-sort.
#pragma unroll
    for (int mask = 1; mask <= 2; mask <<= 1) {
#pragma unroll
        for (int i = 0; i < K_ / 2; i++) {
            u64 oa = __shfl_xor_sync(0xffffffffu, key[K_ - 1 - i], mask); // B[15-i]
            u64 ob = __shfl_xor_sync(0xffffffffu, key[i], mask);          // B[i]
            u64 a_lo = key[i], a_hi = key[K_ - 1 - i];
            key[i]          = a_lo < oa ? a_lo : oa;   // min(A[i],    B[15-i])
            key[K_ - 1 - i] = a_hi < ob ? a_hi : ob;   // min(A[15-i], B[i])
        }
#pragma unroll
        for (int st = 8; st >= 1; st >>= 1) {
#pragma unroll
            for (int i = 0; i < K_; i++) {
                if ((i & st) == 0) {
                    u64 a = key[i], c = key[i + st];
                    key[i] = a < c ? a : c;
                    key[i + st] = a < c ? c : a;
                }
            }
        }
    }

    // Each lane writes its quarter (entries 4*lane .. 4*lane+3), coalesced 16B.
    u64 e0, e1, e2, e3;
    if (lane == 0)      { e0 = key[0];  e1 = key[1];  e2 = key[2];  e3 = key[3];  }
    else if (lane == 1) { e0 = key[4];  e1 = key[5];  e2 = key[6];  e3 = key[7];  }
    else if (lane == 2) { e0 = key[8];  e1 = key[9];  e2 = key[10]; e3 = key[11]; }
    else                { e0 = key[12]; e1 = key[13]; e2 = key[14]; e3 = key[15]; }

    const int tgt = b * M_ + qi;
    float f0 = __fsqrt_rn(__uint_as_float((unsigned)(e0 >> 32)));
    float f1 = __fsqrt_rn(__uint_as_float((unsigned)(e1 >> 32)));
    float f2 = __fsqrt_rn(__uint_as_float((unsigned)(e2 >> 32)));
    float f3 = __fsqrt_rn(__uint_as_float((unsigned)(e3 >> 32)));

    ((float4*)(out + OFF_EIDX))[tgt * 4 + lane] =
        make_float4((float)(b * M_ + (int)(e0 & 0xFFFFFFFFu)),
                    (float)(b * M_ + (int)(e1 & 0xFFFFFFFFu)),
                    (float)(b * M_ + (int)(e2 & 0xFFFFFFFFu)),
                    (float)(b * M_ + (int)(e3 & 0xFFFFFFFFu)));
    ((float4*)(out + OFF_EW))[tgt * 4 + lane] = make_float4(f0, f1, f2, f3);

    // Global max: key[15] is this query's largest kept distance (identical on
    // all 4 lanes post-merge). Warp-reduce then one atomic per warp.
    float lm = __fsqrt_rn(__uint_as_float((unsigned)(key[K_ - 1] >> 32)));
#pragma unroll
    for (int off = 16; off; off >>= 1)
        lm = fmaxf(lm, __shfl_xor_sync(0xffffffffu, lm, off));
    if ((threadIdx.x & 31) == 0)
        atomicMax(&g_maxbits, __float_as_uint(lm));
}

// ---------------------------------------------------------------------------
// K5: normalize edge weights; also zero g_cnt for the NEXT call
// (g_cnt is not read by this kernel -> no ordering hazard).
// ---------------------------------------------------------------------------
__global__ void norm_kernel(float* __restrict__ out) {
    int t = blockIdx.x * blockDim.x + threadIdx.x;
    if (t < B_ * (GG_ + 1)) ((int*)g_cnt)[t] = 0;
    if (t < NE_ / 4) {
        float m = __uint_as_float(g_maxbits);
        float4 v = ((const float4*)(out + OFF_EW))[t];
        ((float4*)(out + OFF_EW))[t] =
            make_float4(v.x / m, v.y / m, v.z / m, v.w / m);
    }
}

extern "C" void kernel_launch(void* const* d_in, const int* in_sizes, int n_in,
                              void* d_out, int out_size) {
    const float* x     = (const float*)d_in[0];
    const float* pos   = (const float*)d_in[1];
    const int*   perm  = (const int*)d_in[5];
    const float* score = (const float*)d_in[6];
    float* out = (float*)d_out;

    const int prep_threads = (N_ * 64) / 16 + N_ + NE_ / 4 + 3 * (N_ / 4);
    prep_kernel<<<prep_threads / 256, 256>>>(x, pos, perm, score, out);

    scan_kernel<<<B_, 1024>>>();
    scatter_kernel<<<N_ / 256, 256>>>(out);
    knn_kernel<<<(4 * N_) / 128, 128>>>(out);     // 4 lanes/query, row segments
    norm_kernel<<<(NE_ / 4) / 256, 256>>>(out);
}

// round 13
// speedup vs baseline: 1.7672x; 1.0531x over previous
#include <cuda_runtime.h>
#include <math_constants.h>

// Problem constants (KnnEdges: B=4, M=8192, D=2, k=16)
#define B_   4
#define M_   8192
#define N_   (B_ * M_)          // 32768
#define K_   16
#define NE_  (N_ * K_)          // 524288

// Spatial grid: cell = 16.0 (power of two -> exact binning/bounds), 63x63 cells
#define G_    63
#define GG_   (G_ * G_)         // 3969
#define INVH_ 0.0625f

// Output layout (float32 concat of reference tuple)
#define OFF_X     0
#define OFF_POSP  2097152
#define OFF_EIDX  2162688
#define OFF_EW    3211264
#define OFF_BATCH 3735552
#define OFF_PERM  3768320
#define OFF_SCORE 3801088

typedef unsigned long long u64;

__device__ int      g_cnt[B_][GG_ + 1];  // counts -> starts; zeroed by norm (prev call) / static init
__device__ int      g_rank[N_];          // per-point rank within its cell
__device__ float4   g_pts[N_];           // grid-sorted (x, y, idx_bits, 0)
__device__ unsigned g_maxbits;           // zeroed by scan_scatter (before knn)

__device__ __forceinline__ int cell_of(float v) {
    int c = (int)(v * INVH_);
    return c > G_ - 1 ? G_ - 1 : (c < 0 ? 0 : c);
}

// ---------------------------------------------------------------------------
// K1: copies/casts + pos gather + cell counting (rank saved for atomic-free
// scatter). Requires g_cnt == 0 on entry (norm of previous call / static).
// batch/perm are int32 on device (JAX x64 disabled).
// ---------------------------------------------------------------------------
__global__ void prep_kernel(const float* __restrict__ x,
                            const float* __restrict__ pos,
                            const int* __restrict__ perm,
                            const float* __restrict__ score,
                            float* __restrict__ out) {
    int t = blockIdx.x * blockDim.x + threadIdx.x;

    const int C0 = (N_ * 64) / 16;         // 131072: x copy, 4 float4 each (ILP)
    if (t < C0) {
        const float4* xs = (const float4*)x;
        float4* xd = (float4*)(out + OFF_X);
        float4 a = xs[t], b = xs[t + C0], c = xs[t + 2 * C0], d = xs[t + 3 * C0];
        xd[t] = a; xd[t + C0] = b; xd[t + 2 * C0] = c; xd[t + 3 * C0] = d;
        return;
    }
    t -= C0;
    if (t < N_) {                          // pos gather + cell count
        int p = perm[t];
        float2 v = ((const float2*)pos)[p];
        ((float2*)(out + OFF_POSP))[t] = v;
        int b = t >> 13;
        int c = cell_of(v.y) * G_ + cell_of(v.x);
        g_rank[t] = atomicAdd(&g_cnt[b][c], 1);
        return;
    }
    t -= N_;
    if (t < NE_ / 4) {                     // tgt row of edge_index, float4
        int base = 4 * t;
        ((float4*)(out + OFF_EIDX + NE_))[t] =
            make_float4((float)(base >> 4), (float)((base + 1) >> 4),
                        (float)((base + 2) >> 4), (float)((base + 3) >> 4));
        return;
    }
    t -= NE_ / 4;
    if (t < N_ / 4) {                      // batch cast, float4
        int base = 4 * t;
        ((float4*)(out + OFF_BATCH))[t] =
            make_float4((float)(base >> 13), (float)((base + 1) >> 13),
                        (float)((base + 2) >> 13), (float)((base + 3) >> 13));
        return;
    }
    t -= N_ / 4;
    if (t < N_ / 4) {                      // perm cast, float4
        int4 p = ((const int4*)perm)[t];
        ((float4*)(out + OFF_PERM))[t] =
            make_float4((float)p.x, (float)p.y, (float)p.z, (float)p.w);
        return;
    }
    t -= N_ / 4;
    if (t < N_ / 4) {                      // score copy, float4
        ((float4*)(out + OFF_SCORE))[t] = ((const float4*)score)[t];
        return;
    }
}

// ---------------------------------------------------------------------------
// K2: fused per-batch scan + scatter (one CTA of 1024 per batch).
// Computes exclusive starts (shared + g_cnt), then scatters points into
// grid-sorted order using saved ranks. Also zeroes g_maxbits.
// ---------------------------------------------------------------------------
__global__ void __launch_bounds__(1024) scan_scatter_kernel(const float* __restrict__ out) {
    __shared__ int ssum[1024];
    __shared__ int sstart[GG_ + 1];
    const int b = blockIdx.x;
    const int t = threadIdx.x;
    const int base = t * 4;

    if (b == 0 && t == 0) g_maxbits = 0u;

    int v[4], tot = 0;
#pragma unroll
    for (int i = 0; i < 4; i++) {
        v[i] = (base + i < GG_) ? g_cnt[b][base + i] : 0;
        tot += v[i];
    }
    ssum[t] = tot;
    __syncthreads();
    for (int off = 1; off < 1024; off <<= 1) {
        int u = (t >= off) ? ssum[t - off] : 0;
        __syncthreads();
        ssum[t] += u;
        __syncthreads();
    }
    int run = ssum[t] - tot;   // exclusive
#pragma unroll
    for (int i = 0; i < 4; i++) {
        if (base + i < GG_) { sstart[base + i] = run; g_cnt[b][base + i] = run; }
        run += v[i];
    }
    if (t == 1023) { sstart[GG_] = run; g_cnt[b][GG_] = run; }   // = M_
    __syncthreads();

    for (int i = t; i < M_; i += 1024) {
        int gi = b * M_ + i;
        float2 v2 = ((const float2*)(out + OFF_POSP))[gi];
        int c = cell_of(v2.y) * G_ + cell_of(v2.x);
        int dst = sstart[c] + g_rank[gi];
        g_pts[b * M_ + dst] = make_float4(v2.x, v2.y, __int_as_float(i), 0.0f);
    }
}

// ---------------------------------------------------------------------------
// K3: exact KNN, 4 cooperative lanes per query.
// Phase A: the 5x5 cell block (rings 0..2) scanned as 5 full-width row
//   segments in CENTER-OUT order (cy, cy-1, cy+1, cy-2, cy+2) -- nearest
//   candidates first so the gate tightens fastest; straight-line, break-free.
//   Visit order does not affect the kept set (top-16 is order-invariant).
// Phase B: rings from r=3 (proven R12 code) for sparse-region stragglers.
// - Lanes split candidates within each row segment (j = js+lane, step 4).
// - Sorted per-lane top-16 of packed u64 keys (d2_bits<<32 | idx); predicated
//   full bubble on insert. Key order == (d2 asc, idx asc) == top_k(-d2).
// - EXACT early-reject gate (proven R11): X = max over the 4 lanes of key[3]
//   (updated per row / per ring; warp-uniform). Union of lanes' top-4s = 16
//   real keys => globalTop16thKey <= X. Any final global top-16 member m
//   arriving at a lane satisfies m < its lane's key[15] and m < X, so
//   skipping candidates with d2_bits > hi32(min(key[15], X)) is lossless
//   (hi-32 equality falls through to the exact u64 check).
// - Termination: sum over lanes of #(kept keys < ((r-1)*16)^2) >= 16 with
//   rings < r fully visited; after phase A that is r=3 (bound 32). Exact.
// - Merge (exact, in-place, 2 temps; proven R8/R9): two rounds (XOR 1, 2).
// - d2 uses explicit rn ops (no FMA) to bit-match XLA's sub/mul/mul/add.
// ---------------------------------------------------------------------------
__global__ void __launch_bounds__(128) knn_kernel(float* __restrict__ out) {
    const int t     = blockIdx.x * 128 + threadIdx.x;
    const int group = t >> 2;          // query id
    const int lane  = t & 3;
    const int b     = group >> 13;
    const int s     = group & (M_ - 1);

    const float4* __restrict__ pts = g_pts + b * M_;
    const int*    __restrict__ cs  = g_cnt[b];

    float4 q = pts[s];
    const int qi = __float_as_int(q.z);
    const int cx = cell_of(q.x), cy = cell_of(q.y);

    u64 key[K_];
#pragma unroll
    for (int u = 0; u < K_; u++) key[u] = 0xFFFFFFFFFFFFFFFFull;

    unsigned gate_hi = 0xFFFFFFFFu;

// One contiguous row segment of cells [XA..XB] in row YY.
#define VISIT_SEG(XA, XB, YY)                                                  \
    {                                                                          \
        int c0_ = (YY) * G_ + (XA);                                            \
        int js_ = cs[c0_], je_ = cs[c0_ + ((XB) - (XA)) + 1];                  \
        for (int j_ = js_ + lane; j_ < je_; j_ += 4) {                         \
            float4 v_ = pts[j_];                                               \
            float dx_ = __fsub_rn(q.x, v_.x);                                  \
            float dy_ = __fsub_rn(q.y, v_.y);                                  \
            float d2_ = __fadd_rn(__fmul_rn(dx_, dx_), __fmul_rn(dy_, dy_));   \
            unsigned d2u_ = __float_as_uint(d2_);                              \
            if (d2u_ <= gate_hi) {                                             \
                u64 nk_ = ((u64)d2u_ << 32) |                                  \
                          (unsigned)__float_as_int(v_.z);                      \
                if (nk_ < key[K_ - 1]) {                                       \
                    key[K_ - 1] = nk_;                                         \
                    _Pragma("unroll")                                          \
                    for (int u_ = K_ - 1; u_ > 0; u_--) {                      \
                        if (key[u_] < key[u_ - 1]) {                           \
                            u64 tm_ = key[u_]; key[u_] = key[u_ - 1];          \
                            key[u_ - 1] = tm_;                                 \
                        }                                                      \
                    }                                                          \
                }                                                              \
            }                                                                  \
        }                                                                      \
    }

// Gate update: X = max over 4 lanes of key[3]; gate = min(key[15], X) hi-32.
#define UPDATE_GATE()                                                          \
    {                                                                          \
        u64 x3 = key[3];                                                       \
        u64 o_ = __shfl_xor_sync(0xffffffffu, x3, 1);                          \
        if (o_ > x3) x3 = o_;                                                  \
        o_ = __shfl_xor_sync(0xffffffffu, x3, 2);                              \
        if (o_ > x3) x3 = o_;                                                  \
        u64 g_ = key[K_ - 1] < x3 ? key[K_ - 1] : x3;                          \
        gate_hi = (unsigned)(g_ >> 32);                                        \
    }

    // ---- Phase A: 5x5 block, rows center-out ----
    {
        int xa = cx - 2 < 0 ? 0 : cx - 2;
        int xb = cx + 2 > G_ - 1 ? G_ - 1 : cx + 2;
        VISIT_SEG(xa, xb, cy);
        UPDATE_GATE();
        if (cy - 1 >= 0)      VISIT_SEG(xa, xb, cy - 1);
        if (cy + 1 <= G_ - 1) VISIT_SEG(xa, xb, cy + 1);
        UPDATE_GATE();
        if (cy - 2 >= 0)      VISIT_SEG(xa, xb, cy - 2);
        if (cy + 2 <= G_ - 1) VISIT_SEG(xa, xb, cy + 2);
    }

    // ---- Phase B: rings from r=3 (rings 0..2 fully visited above) ----
    bool done = false;
    for (int r = 3; r < G_; r++) {
        {
            float bnd = (float)(r - 1) * 16.0f;     // exact in fp
            float B2 = bnd * bnd;
            int cnt = 0;
#pragma unroll
            for (int u = 0; u < K_; u++)
                cnt += (__uint_as_float((unsigned)(key[u] >> 32)) < B2) ? 1 : 0;
            cnt += __shfl_xor_sync(0xffffffffu, cnt, 1);
            cnt += __shfl_xor_sync(0xffffffffu, cnt, 2);
            if (cnt >= K_) done = true;
        }
        if (__all_sync(0xffffffffu, done)) break;
        UPDATE_GATE();
        if (!done) {
            int x0 = cx - r, x1 = cx + r, y0 = cy - r, y1 = cy + r;
            int xa = x0 < 0 ? 0 : x0, xb = x1 > G_ - 1 ? G_ - 1 : x1;
            if (y0 >= 0)      VISIT_SEG(xa, xb, y0);   // top row
            if (y1 <= G_ - 1) VISIT_SEG(xa, xb, y1);   // bottom row
            int ya = (y0 + 1) < 0 ? 0 : (y0 + 1);
            int yb = (y1 - 1) > G_ - 1 ? G_ - 1 : (y1 - 1);
            for (int yy = ya; yy <= yb; yy++) {        // side columns
                if (x0 >= 0)      VISIT_SEG(x0, x0, yy);
                if (x1 <= G_ - 1) VISIT_SEG(x1, x1, yy);
            }
        }
    }
#undef VISIT_SEG
#undef UPDATE_GATE

    // Two rounds of exact in-place cross-lane merge + bitonic re-sort.
#pragma unroll
    for (int mask = 1; mask <= 2; mask <<= 1) {
#pragma unroll
        for (int i = 0; i < K_ / 2; i++) {
            u64 oa = __shfl_xor_sync(0xffffffffu, key[K_ - 1 - i], mask); // B[15-i]
            u64 ob = __shfl_xor_sync(0xffffffffu, key[i], mask);          // B[i]
            u64 a_lo = key[i], a_hi = key[K_ - 1 - i];
            key[i]          = a_lo < oa ? a_lo : oa;   // min(A[i],    B[15-i])
            key[K_ - 1 - i] = a_hi < ob ? a_hi : ob;   // min(A[15-i], B[i])
        }
#pragma unroll
        for (int st = 8; st >= 1; st >>= 1) {
#pragma unroll
            for (int i = 0; i < K_; i++) {
                if ((i & st) == 0) {
                    u64 a = key[i], c = key[i + st];
                    key[i] = a < c ? a : c;
                    key[i + st] = a < c ? c : a;
                }
            }
        }
    }

    // Each lane writes its quarter (entries 4*lane .. 4*lane+3), coalesced 16B.
    u64 e0, e1, e2, e3;
    if (lane == 0)      { e0 = key[0];  e1 = key[1];  e2 = key[2];  e3 = key[3];  }
    else if (lane == 1) { e0 = key[4];  e1 = key[5];  e2 = key[6];  e3 = key[7];  }
    else if (lane == 2) { e0 = key[8];  e1 = key[9];  e2 = key[10]; e3 = key[11]; }
    else                { e0 = key[12]; e1 = key[13]; e2 = key[14]; e3 = key[15]; }

    const int tgt = b * M_ + qi;
    float f0 = __fsqrt_rn(__uint_as_float((unsigned)(e0 >> 32)));
    float f1 = __fsqrt_rn(__uint_as_float((unsigned)(e1 >> 32)));
    float f2 = __fsqrt_rn(__uint_as_float((unsigned)(e2 >> 32)));
    float f3 = __fsqrt_rn(__uint_as_float((unsigned)(e3 >> 32)));

    ((float4*)(out + OFF_EIDX))[tgt * 4 + lane] =
        make_float4((float)(b * M_ + (int)(e0 & 0xFFFFFFFFu)),
                    (float)(b * M_ + (int)(e1 & 0xFFFFFFFFu)),
                    (float)(b * M_ + (int)(e2 & 0xFFFFFFFFu)),
                    (float)(b * M_ + (int)(e3 & 0xFFFFFFFFu)));
    ((float4*)(out + OFF_EW))[tgt * 4 + lane] = make_float4(f0, f1, f2, f3);

    // Global max: key[15] is this query's largest kept distance (identical on
    // all 4 lanes post-merge). Warp-reduce then one atomic per warp.
    float lm = __fsqrt_rn(__uint_as_float((unsigned)(key[K_ - 1] >> 32)));
#pragma unroll
    for (int off = 16; off; off >>= 1)
        lm = fmaxf(lm, __shfl_xor_sync(0xffffffffu, lm, off));
    if ((threadIdx.x & 31) == 0)
        atomicMax(&g_maxbits, __float_as_uint(lm));
}

// ---------------------------------------------------------------------------
// K4: normalize edge weights; also zero g_cnt for the NEXT call
// (g_cnt is not read by this kernel -> no ordering hazard).
// ---------------------------------------------------------------------------
__global__ void norm_kernel(float* __restrict__ out) {
    int t = blockIdx.x * blockDim.x + threadIdx.x;
    if (t < B_ * (GG_ + 1)) ((int*)g_cnt)[t] = 0;
    if (t < NE_ / 4) {
        float m = __uint_as_float(g_maxbits);
        float4 v = ((const float4*)(out + OFF_EW))[t];
        ((float4*)(out + OFF_EW))[t] =
            make_float4(v.x / m, v.y / m, v.z / m, v.w / m);
    }
}

extern "C" void kernel_launch(void* const* d_in, const int* in_sizes, int n_in,
                              void* d_out, int out_size) {
    const float* x     = (const float*)d_in[0];
    const float* pos   = (const float*)d_in[1];
    const int*   perm  = (const int*)d_in[5];
    const float* score = (const float*)d_in[6];
    float* out = (float*)d_out;

    const int prep_threads = (N_ * 64) / 16 + N_ + NE_ / 4 + 3 * (N_ / 4);
    prep_kernel<<<prep_threads / 256, 256>>>(x, pos, perm, score, out);

    scan_scatter_kernel<<<B_, 1024>>>(out);
    knn_kernel<<<(4 * N_) / 128, 128>>>(out);     // 4 lanes/query, 5x5 + rings
    norm_kernel<<<(NE_ / 4) / 256, 256>>>(out);
}